// round 3
// baseline (speedup 1.0000x reference)
#include <cuda_runtime.h>

// NeuralODE fused RK4 persistent kernel.
// B=1024 rows, D=256, H=1024, 8 RK4 steps (32 MLP evals).
// Row-independent: each CTA integrates M_BLK=8 rows start-to-finish.
// Weights (W1: 256x1024, W2: 1024x256, 2MB total) streamed from L2 each eval.

namespace {
constexpr int Bn     = 1024;
constexpr int Dn     = 256;
constexpr int Hn     = 1024;
constexpr int NSTEPS = 8;
constexpr int MBLK   = 8;
constexpr int NTHR   = 256;
constexpr int GRID   = Bn / MBLK;   // 128 CTAs
}

__device__ __forceinline__ float tanha(float x) {
    float y;
    asm("tanh.approx.f32 %0, %1;" : "=f"(y) : "f"(x));
    return y;
}

// acc += s * v  (component-wise), as a function to avoid macro token hazards.
__device__ __forceinline__ void fma4(float4& acc, float s, const float4& v) {
    acc.x = fmaf(s, v.x, acc.x);
    acc.y = fmaf(s, v.y, acc.y);
    acc.z = fmaf(s, v.z, acc.z);
    acc.w = fmaf(s, v.w, acc.w);
}

__device__ __forceinline__ float4 f4_axpy(float a, float4 x, float4 y) {
    // y + a*x
    float4 r;
    r.x = fmaf(a, x.x, y.x);
    r.y = fmaf(a, x.y, y.y);
    r.z = fmaf(a, x.z, y.z);
    r.w = fmaf(a, x.w, y.w);
    return r;
}

__device__ __forceinline__ float4 f4_add(float4 a, float4 b) {
    float4 r; r.x=a.x+b.x; r.y=a.y+b.y; r.z=a.z+b.z; r.w=a.w+b.w; return r;
}

__global__ void __launch_bounds__(NTHR, 1) node_rk4_kernel(
    const float* __restrict__ z0, const float* __restrict__ tt,
    const float* __restrict__ W1, const float* __restrict__ b1,
    const float* __restrict__ W2, const float* __restrict__ b2,
    float* __restrict__ out)
{
    __shared__ __align__(16) float s_probe[MBLK][Dn];   //  8 KB : current f() input rows
    __shared__ __align__(16) float s_hid[MBLK][Hn];     // 32 KB : tanh hidden

    const int tid  = threadIdx.x;
    const int row0 = blockIdx.x * MBLK;

    const float h  = (tt[1] - tt[0]) / (float)NSTEPS;
    const float h2 = 0.5f * h;
    const float h6 = h * (1.0f / 6.0f);

    // Phase-2 / elementwise ownership: thread owns output cols [4*iw, 4*iw+4)
    // of rows m0 and m0+4.
    const int iw = tid & 63;
    const int m0 = tid >> 6;

    const float4* W1v = reinterpret_cast<const float4*>(W1);
    const float4* W2v = reinterpret_cast<const float4*>(W2);

    const float4 b1v = reinterpret_cast<const float4*>(b1)[tid];  // j = 4*tid..
    const float4 b2v = reinterpret_cast<const float4*>(b2)[iw];   // i = 4*iw..

    // Load z0 rows; keep z_base in registers, mirror into s_probe.
    float4 zb0 = reinterpret_cast<const float4*>(z0)[(row0 + m0)     * (Dn/4) + iw];
    float4 zb1 = reinterpret_cast<const float4*>(z0)[(row0 + m0 + 4) * (Dn/4) + iw];
    *reinterpret_cast<float4*>(&s_probe[m0][4*iw])     = zb0;
    *reinterpret_cast<float4*>(&s_probe[m0 + 4][4*iw]) = zb1;
    __syncthreads();

    float4 ac0, ac1;  // RK4 accumulators (k1 + 2k2 + 2k3 + k4)

    for (int step = 0; step < NSTEPS; ++step) {
        #pragma unroll
        for (int e = 0; e < 4; ++e) {
            // ---------- phase 1: hid = tanh(probe @ W1 + b1) ----------
            // thread t owns hidden columns [4t, 4t+4) for all MBLK rows.
            float4 ha[MBLK];
            #pragma unroll
            for (int m = 0; m < MBLK; m++) ha[m] = b1v;

            #pragma unroll 2
            for (int d = 0; d < Dn; d += 4) {
                const float4 wa = W1v[(d + 0) * (Hn/4) + tid];
                const float4 wb = W1v[(d + 1) * (Hn/4) + tid];
                const float4 wc = W1v[(d + 2) * (Hn/4) + tid];
                const float4 wd = W1v[(d + 3) * (Hn/4) + tid];
                #pragma unroll
                for (int m = 0; m < MBLK; m++) {
                    const float4 zv = *reinterpret_cast<const float4*>(&s_probe[m][d]);
                    fma4(ha[m], zv.x, wa);
                    fma4(ha[m], zv.y, wb);
                    fma4(ha[m], zv.z, wc);
                    fma4(ha[m], zv.w, wd);
                }
            }

            #pragma unroll
            for (int m = 0; m < MBLK; m++) {
                float4 tv;
                tv.x = tanha(ha[m].x);
                tv.y = tanha(ha[m].y);
                tv.z = tanha(ha[m].z);
                tv.w = tanha(ha[m].w);
                *reinterpret_cast<float4*>(&s_hid[m][4 * tid]) = tv;
            }
            __syncthreads();

            // ---------- phase 2: k = hid @ W2 + b2 ----------
            float4 k0 = b2v, k1 = b2v;
            #pragma unroll 2
            for (int j = 0; j < Hn; j += 4) {
                const float4 wa = W2v[(j + 0) * (Dn/4) + iw];
                const float4 wb = W2v[(j + 1) * (Dn/4) + iw];
                const float4 wc = W2v[(j + 2) * (Dn/4) + iw];
                const float4 wd = W2v[(j + 3) * (Dn/4) + iw];
                const float4 h0 = *reinterpret_cast<const float4*>(&s_hid[m0][j]);
                const float4 h1 = *reinterpret_cast<const float4*>(&s_hid[m0 + 4][j]);
                fma4(k0, h0.x, wa); fma4(k0, h0.y, wb);
                fma4(k0, h0.z, wc); fma4(k0, h0.w, wd);
                fma4(k1, h1.x, wa); fma4(k1, h1.y, wb);
                fma4(k1, h1.z, wc); fma4(k1, h1.w, wd);
            }

            // ---------- RK4 elementwise glue (registers only) ----------
            float4 p0, p1;
            if (e == 0) {
                ac0 = k0;                       ac1 = k1;
                p0  = f4_axpy(h2, k0, zb0);     p1  = f4_axpy(h2, k1, zb1);
            } else if (e == 1) {
                ac0 = f4_axpy(2.0f, k0, ac0);   ac1 = f4_axpy(2.0f, k1, ac1);
                p0  = f4_axpy(h2, k0, zb0);     p1  = f4_axpy(h2, k1, zb1);
            } else if (e == 2) {
                ac0 = f4_axpy(2.0f, k0, ac0);   ac1 = f4_axpy(2.0f, k1, ac1);
                p0  = f4_axpy(h, k0, zb0);      p1  = f4_axpy(h, k1, zb1);
            } else {
                ac0 = f4_add(ac0, k0);          ac1 = f4_add(ac1, k1);
                zb0 = f4_axpy(h6, ac0, zb0);    zb1 = f4_axpy(h6, ac1, zb1);
                p0  = zb0;                      p1  = zb1;
            }
            *reinterpret_cast<float4*>(&s_probe[m0][4*iw])     = p0;
            *reinterpret_cast<float4*>(&s_probe[m0 + 4][4*iw]) = p1;
            __syncthreads();
        }
    }

    reinterpret_cast<float4*>(out)[(row0 + m0)     * (Dn/4) + iw] = zb0;
    reinterpret_cast<float4*>(out)[(row0 + m0 + 4) * (Dn/4) + iw] = zb1;
}

extern "C" void kernel_launch(void* const* d_in, const int* in_sizes, int n_in,
                              void* d_out, int out_size) {
    const float* z0 = (const float*)d_in[0];
    const float* tt = (const float*)d_in[1];
    const float* W1 = (const float*)d_in[2];
    const float* b1 = (const float*)d_in[3];
    const float* W2 = (const float*)d_in[4];
    const float* b2 = (const float*)d_in[5];
    float* out = (float*)d_out;
    (void)in_sizes; (void)n_in; (void)out_size;

    node_rk4_kernel<<<GRID, NTHR>>>(z0, tt, W1, b1, W2, b2, out);
}